// round 8
// baseline (speedup 1.0000x reference)
#include <cuda_runtime.h>

// Problem constants
#define B_  4
#define P_  64
#define S_  8
#define YD  16
#define GD  48
// totals
#define N_KY   (B_ * P_ * S_)           // 2048
#define N_OUT  (B_ * P_ * P_ * S_ * S_) // 1048576

// Scratch for the ky tables (no cudaMalloc allowed)
__device__ float g_ky1[N_KY];  // y @ Wy[:16]           -> indexed by (b, p2, s2)
__device__ float g_ky2[N_KY];  // y @ Wy[16:] + by + bg -> indexed by (b, p1, s1)

// Kernel 1: build ky tables. 2048 threads, each does a 16-wide dot twice.
__global__ void ky_kernel(const float* __restrict__ y,
                          const float* __restrict__ Wy,
                          const float* __restrict__ by,
                          const float* __restrict__ bg) {
    int i = blockIdx.x * blockDim.x + threadIdx.x;  // (b*P + p)*S + s
    if (i >= N_KY) return;
    const float4* y4 = reinterpret_cast<const float4*>(y + (size_t)i * YD);
    float a1 = 0.f, a2 = 0.f;
#pragma unroll
    for (int j = 0; j < YD / 4; j++) {
        float4 yv = __ldg(y4 + j);
        float4 w1 = __ldg(reinterpret_cast<const float4*>(Wy) + j);
        float4 w2 = __ldg(reinterpret_cast<const float4*>(Wy + YD) + j);
        a1 += yv.x * w1.x + yv.y * w1.y + yv.z * w1.z + yv.w * w1.w;
        a2 += yv.x * w2.x + yv.y * w2.y + yv.z * w2.z + yv.w * w2.w;
    }
    g_ky1[i] = a1;
    g_ky2[i] = a2 + by[0] + bg[0];  // fold biases in once
}

// Kernel 2: main stream. One thread per output element; 12x float4 loads of
// pairwise_g (192 B/thread, MLP=12), dot with Wg held in shared memory.
__global__ void __launch_bounds__(256) main_kernel(
    const float* __restrict__ pg,
    const float* __restrict__ Wg,
    float* __restrict__ out) {
    __shared__ float wg_sh[GD];
    if (threadIdx.x < GD) wg_sh[threadIdx.x] = Wg[threadIdx.x];
    __syncthreads();

    int o = blockIdx.x * blockDim.x + threadIdx.x;
    if (o >= N_OUT) return;

    // o = (((b*P + p1)*P + p2)*S + s1)*S + s2
    int s2 = o & (S_ - 1);
    int t  = o >> 3;
    int s1 = t & (S_ - 1);
    t >>= 3;
    int p2 = t & (P_ - 1);
    t >>= 6;
    int p1 = t & (P_ - 1);
    int b  = t >> 6;

    const float4* g4 = reinterpret_cast<const float4*>(pg + (size_t)o * GD);
    const float4* w4 = reinterpret_cast<const float4*>(wg_sh);

    float acc = 0.f;
#pragma unroll
    for (int j = 0; j < GD / 4; j++) {
        float4 gv = __ldg(g4 + j);
        float4 wv = w4[j];
        acc += gv.x * wv.x + gv.y * wv.y + gv.z * wv.z + gv.w * wv.w;
    }

    float ky1 = g_ky1[(b * P_ + p2) * S_ + s2];
    float ky2 = g_ky2[(b * P_ + p1) * S_ + s1];  // includes by+bg
    out[o] = acc + ky1 + ky2;
}

extern "C" void kernel_launch(void* const* d_in, const int* in_sizes, int n_in,
                              void* d_out, int out_size) {
    // metadata order: y, pairwise_g, Wy, by, Wg, bg
    const float* y  = (const float*)d_in[0];
    const float* pg = (const float*)d_in[1];
    const float* Wy = (const float*)d_in[2];
    const float* by = (const float*)d_in[3];
    const float* Wg = (const float*)d_in[4];
    const float* bg = (const float*)d_in[5];
    float* out = (float*)d_out;

    ky_kernel<<<(N_KY + 255) / 256, 256>>>(y, Wy, by, bg);
    main_kernel<<<(N_OUT + 255) / 256, 256>>>(pg, Wg, out);
}